// round 17
// baseline (speedup 1.0000x reference)
#include <cuda_runtime.h>
#include <math.h>
#include <stdint.h>

#define SEQ 2048
#define DIM 1280
#define NH  16
#define HD  80
#define RBX (SEQ / 16)       // 128 row-blocks of 16
#define KBX (DIM / 8)        // 160 k-blocks of 8

// Scratch (device globals)
__device__ float g_Q[SEQ * DIM];          // QKV gemm row-major Q (pre-rope)
__device__ float g_K[SEQ * DIM];          // row-major K (pre-rope)
__device__ float g_Qf[SEQ * DIM];         // roped Q, A-fragment order per (rb,h,kb)
__device__ float g_Kf[SEQ * DIM];         // roped K, B-fragment order per (cbk,h,kb)
__device__ float g_Vtf[SEQ * DIM];        // V^T, B-fragment order per (h,db,kb2)
__device__ float g_Xap[SEQ * DIM];        // X in A-fragment order, tf32
__device__ float g_Aap[SEQ * DIM];        // attention out in A-fragment order, tf32
__device__ float g_Wqkvp[3 * DIM * DIM];  // Wq|Wk|Wv stacked, B-fragment order
__device__ float g_Wop[DIM * DIM];

__device__ __forceinline__ float f2tf32(float x) {
    uint32_t u;
    asm("cvt.rna.tf32.f32 %0, %1;" : "=r"(u) : "f"(x));
    return __uint_as_float(u);
}

__device__ __forceinline__ void mma_tf32(float* c, const uint32_t* a, const uint32_t* b) {
    asm("mma.sync.aligned.m16n8k8.row.col.f32.tf32.tf32.f32 "
        "{%0,%1,%2,%3}, {%4,%5,%6,%7}, {%8,%9}, {%0,%1,%2,%3};"
        : "+f"(c[0]), "+f"(c[1]), "+f"(c[2]), "+f"(c[3])
        : "r"(a[0]), "r"(a[1]), "r"(a[2]), "r"(a[3]), "r"(b[0]), "r"(b[1]));
}

__device__ __forceinline__ void cp16(uint32_t dst, const void* src) {
    asm volatile("cp.async.cg.shared.global [%0], [%1], 16;\n" :: "r"(dst), "l"(src));
}

// ---------------------------------------------------------------------------
// permute_all: X -> A-fragment order; Wq/Wk/Wv stacked + Wo -> B-frag order.
// No padding needed (1280 = 16 tiles of 80 columns).
// ---------------------------------------------------------------------------
#define NXP (RBX * KBX * 32)
#define NWP (KBX * KBX * 32)
__global__ void permute_all(const float* __restrict__ X,
                            const float* __restrict__ Wq, const float* __restrict__ Wk,
                            const float* __restrict__ Wv, const float* __restrict__ Wo)
{
    int i = blockIdx.x * blockDim.x + threadIdx.x;
    if (i < NXP) {
        int lane = i & 31, t = i >> 5;
        int kb = t % KBX, rb = t / KBX;
        int g = lane >> 2, tg = lane & 3;
        int r = rb * 16 + g, c = kb * 8 + tg;
        float4 v;
        v.x = f2tf32(X[(size_t)r * DIM + c]);
        v.y = f2tf32(X[(size_t)(r + 8) * DIM + c]);
        v.z = f2tf32(X[(size_t)r * DIM + c + 4]);
        v.w = f2tf32(X[(size_t)(r + 8) * DIM + c + 4]);
        ((float4*)g_Xap)[i] = v;
        return;
    }
    int j = i - NXP;
    int widx = j / NWP;
    if (widx >= 4) return;
    int k = j - widx * NWP;
    const float* W = (widx == 0) ? Wq : (widx == 1) ? Wk : (widx == 2) ? Wv : Wo;
    float* dst = (widx < 3) ? (g_Wqkvp + (size_t)widx * DIM * DIM) : g_Wop;
    int lane = k & 31, t = k >> 5;
    int kb = t % KBX, cb = t / KBX;
    int g = lane >> 2, tg = lane & 3;
    int r = cb * 8 + g, c = kb * 8 + tg;
    float2 v;
    v.x = f2tf32(W[(size_t)r * DIM + c]);
    v.y = f2tf32(W[(size_t)r * DIM + c + 4]);
    ((float2*)dst)[k] = v;
}

// ---------------------------------------------------------------------------
// TF32 GEMM mainloop, fragment-order operands, OCC 2 (2 CTAs/SM).
// BM=128, BN=80; 8 warps (4m x 2n), warp tile 32x40, acc[2][5][4] = 40 regs.
// Single-buffered fragments (latency hidden by 4 warps/SMSP across 2 CTAs).
// R13-proven sync structure: issue -> wait -> sync -> compute -> sync.
// ---------------------------------------------------------------------------
#define BM 128
#define BN 80
#define BK 32
#define A_STAGE (8 * 4 * 128)      // 4096 floats
#define B_STAGE (10 * 4 * 64)      // 2560 floats
#define STAGEF (A_STAGE + B_STAGE) // 6656
#define GEMM_SMEM (2 * STAGEF * 4) // 53248 B

__device__ __forceinline__ void gemm_mainloop(
    const float* __restrict__ Aap, const float* __restrict__ Bbp,
    float* sm, int rb0, int cb0, int tid, int wm, int wn, int lane,
    float acc[2][5][4])
{
    const uint32_t sbase = (uint32_t)__cvta_generic_to_shared(sm);
    const int T = DIM / BK;   // 40

    auto issue = [&](int stage, int kt) {
        const int kb0 = kt >> 3;
        const uint32_t base = sbase + (uint32_t)stage * STAGEF * 4u;
#pragma unroll
        for (int t = 0; t < 4; t++) {          // A: 1024 16B-chunks
            int ci = tid + t * 256;
            int blk = ci >> 5;
            int rb_l = blk >> 2, kb_l = blk & 3;
            int l16 = ci & 31;
            cp16(base + (uint32_t)(blk * 128 + l16 * 4) * 4u,
                 Aap + ((size_t)(rb0 + rb_l) * KBX + kb0 + kb_l) * 128 + l16 * 4);
        }
#pragma unroll
        for (int t = 0; t < 3; t++) {          // B: 640 16B-chunks
            int ci = tid + t * 256;
            if (ci < 640) {
                int blk = ci >> 4;             // cb_l*4 + kb_l (0..39)
                int cb_l = blk >> 2, kb_l = blk & 3;
                int l16 = ci & 15;
                cp16(base + (uint32_t)(A_STAGE + blk * 64 + l16 * 4) * 4u,
                     Bbp + ((size_t)(cb0 + cb_l) * KBX + kb0 + kb_l) * 64 + l16 * 4);
            }
        }
        asm volatile("cp.async.commit_group;\n");
    };

    issue(0, 0);

    for (int ti = 0; ti < T; ti++) {
        if (ti + 1 < T) {
            issue((ti + 1) & 1, (ti + 1) * BK);
            asm volatile("cp.async.wait_group 1;\n");
        } else {
            asm volatile("cp.async.wait_group 0;\n");
        }
        __syncthreads();

        const float* Asr = sm + (ti & 1) * STAGEF;
        const float* Bsr = Asr + A_STAGE;

#pragma unroll
        for (int ks = 0; ks < 4; ks++) {
            uint32_t af[2][4], bf[5][2];
#pragma unroll
            for (int mt = 0; mt < 2; mt++) {
                float4 v = *(const float4*)(Asr + ((wm * 2 + mt) * 4 + ks) * 128 + lane * 4);
                af[mt][0] = __float_as_uint(v.x);
                af[mt][1] = __float_as_uint(v.y);
                af[mt][2] = __float_as_uint(v.z);
                af[mt][3] = __float_as_uint(v.w);
            }
#pragma unroll
            for (int nt = 0; nt < 5; nt++) {
                float2 v = *(const float2*)(Bsr + ((wn * 5 + nt) * 4 + ks) * 64 + lane * 2);
                bf[nt][0] = __float_as_uint(v.x);
                bf[nt][1] = __float_as_uint(v.y);
            }
#pragma unroll
            for (int mt = 0; mt < 2; mt++)
#pragma unroll
                for (int nt = 0; nt < 5; nt++)
                    mma_tf32(acc[mt][nt], af[mt], bf[nt]);
        }
        __syncthreads();
    }
}

// ---------------------------------------------------------------------------
// Fused QKV GEMM: grid (48, 16). seg = bx/16 routes output:
// 0 -> g_Q rows, 1 -> g_K rows, 2 -> g_Vtf fragments.
// ---------------------------------------------------------------------------
__global__ __launch_bounds__(256, 2)
void gemm_qkv(const float* __restrict__ Aap,
              const float* __restrict__ bq, const float* __restrict__ bk,
              const float* __restrict__ bv)
{
    extern __shared__ float sm[];
    const int tid = threadIdx.x;
    const int m0 = blockIdx.y * BM;
    const int rb0 = m0 >> 4;
    const int seg = blockIdx.x >> 4;          // 0:Q 1:K 2:V
    const int bxl = blockIdx.x & 15;
    const int n0 = bxl * BN;
    const int cb0 = bxl * 10;
    const float* Bptr = g_Wqkvp + (size_t)seg * DIM * DIM;

    const int warp = tid >> 5, lane = tid & 31;
    const int wm = warp >> 1, wn = warp & 1;
    const int g = lane >> 2, tg = lane & 3;

    float acc[2][5][4];
#pragma unroll
    for (int mt = 0; mt < 2; mt++)
#pragma unroll
        for (int nt = 0; nt < 5; nt++)
#pragma unroll
            for (int r = 0; r < 4; r++) acc[mt][nt][r] = 0.f;

    gemm_mainloop(Aap, Bptr, sm, rb0, cb0, tid, wm, wn, lane, acc);

    const float* bias = (seg == 0) ? bq : (seg == 1) ? bk : bv;
    float* Crow = (seg == 0) ? g_Q : g_K;

    auto vtf_store = [&](int key, int c, float val) {
        int h = c / HD, dd = c % HD;
        int db = dd >> 3, gq = dd & 7;
        int kb2 = key >> 3, tgq = key & 7;
        int lanef = gq * 4 + (tgq & 3);
        int comp = (tgq < 4) ? 0 : 1;
        g_Vtf[((((size_t)h * 10 + db) * 256 + kb2) * 32 + lanef) * 2 + comp] = val;
    };

#pragma unroll
    for (int mt = 0; mt < 2; mt++) {
#pragma unroll
        for (int nt = 0; nt < 5; nt++) {
            int r = m0 + wm * 32 + mt * 16 + g;
            int c = n0 + wn * 40 + nt * 8 + 2 * tg;
            float b0 = bias[c];
            float b1 = bias[c + 1];
            if (seg < 2) {
                Crow[(size_t)r * DIM + c]           = acc[mt][nt][0] + b0;
                Crow[(size_t)(r + 8) * DIM + c]     = acc[mt][nt][2] + b0;
                Crow[(size_t)r * DIM + c + 1]       = acc[mt][nt][1] + b1;
                Crow[(size_t)(r + 8) * DIM + c + 1] = acc[mt][nt][3] + b1;
            } else {
                vtf_store(r,     c,     f2tf32(acc[mt][nt][0] + b0));
                vtf_store(r + 8, c,     f2tf32(acc[mt][nt][2] + b0));
                vtf_store(r,     c + 1, f2tf32(acc[mt][nt][1] + b1));
                vtf_store(r + 8, c + 1, f2tf32(acc[mt][nt][3] + b1));
            }
        }
    }
}

// ---------------------------------------------------------------------------
// O-projection GEMM: grid (16, 16) = 256 CTAs, row-major out.
// ---------------------------------------------------------------------------
__global__ __launch_bounds__(256, 2)
void gemm_o(const float* __restrict__ Aap, const float* __restrict__ bias,
            float* __restrict__ C)
{
    extern __shared__ float sm[];
    const int tid = threadIdx.x;
    const int m0 = blockIdx.y * BM;
    const int n0 = blockIdx.x * BN;
    const int rb0 = m0 >> 4;
    const int cb0 = blockIdx.x * 10;

    const int warp = tid >> 5, lane = tid & 31;
    const int wm = warp >> 1, wn = warp & 1;
    const int g = lane >> 2, tg = lane & 3;

    float acc[2][5][4];
#pragma unroll
    for (int mt = 0; mt < 2; mt++)
#pragma unroll
        for (int nt = 0; nt < 5; nt++)
#pragma unroll
            for (int r = 0; r < 4; r++) acc[mt][nt][r] = 0.f;

    gemm_mainloop(Aap, g_Wop, sm, rb0, cb0, tid, wm, wn, lane, acc);

#pragma unroll
    for (int mt = 0; mt < 2; mt++) {
#pragma unroll
        for (int nt = 0; nt < 5; nt++) {
            int r = m0 + wm * 32 + mt * 16 + g;
            int c = n0 + wn * 40 + nt * 8 + 2 * tg;
            float b0 = bias[c];
            float b1 = bias[c + 1];
            C[(size_t)r * DIM + c]           = acc[mt][nt][0] + b0;
            C[(size_t)(r + 8) * DIM + c]     = acc[mt][nt][2] + b0;
            C[(size_t)r * DIM + c + 1]       = acc[mt][nt][1] + b1;
            C[(size_t)(r + 8) * DIM + c + 1] = acc[mt][nt][3] + b1;
        }
    }
}

// ---------------------------------------------------------------------------
// RoPE -> fragment-order g_Qf (A, Q pre-scaled) and g_Kf (B).
// ---------------------------------------------------------------------------
#define NQP (RBX * NH * 5 * 32)
#define NKP ((SEQ / 8) * NH * 5 * 32)
__global__ void rope_frag(const float* __restrict__ cs, const float* __restrict__ sn)
{
    int i = blockIdx.x * blockDim.x + threadIdx.x;
    const float scale = rsqrtf((float)HD);
    if (i < NQP) {
        int lane = i & 31, t = i >> 5;
        int kbp = t % 5, h = (t / 5) % NH, rbq = t / (5 * NH);
        int g = lane >> 2, tg = lane & 3;
        int r = rbq * 16 + g;
        int cc = kbp * 8 + tg;
        const float* q0 = g_Q + (size_t)r * DIM + h * HD;
        const float* q1 = g_Q + (size_t)(r + 8) * DIM + h * HD;
        float x0[4] = {q0[cc], q1[cc], q0[cc + 4], q1[cc + 4]};
        float x1[4] = {q0[cc + 40], q1[cc + 40], q0[cc + 44], q1[cc + 44]};
        int rr[4] = {r, r + 8, r, r + 8};
        int jc[4] = {cc, cc, cc + 4, cc + 4};
        float4 o0, o1;
        float* o0p = &o0.x; float* o1p = &o1.x;
#pragma unroll
        for (int q = 0; q < 4; q++) {
            float c0 = cs[rr[q] * HD + jc[q]],      s0 = sn[rr[q] * HD + jc[q]];
            float c1 = cs[rr[q] * HD + jc[q] + 40], s1 = sn[rr[q] * HD + jc[q] + 40];
            o0p[q] = f2tf32((x0[q] * c0 - x1[q] * s0) * scale);
            o1p[q] = f2tf32((x1[q] * c1 + x0[q] * s1) * scale);
        }
        size_t base = ((size_t)(rbq * NH + h) * 10);
        ((float4*)g_Qf)[(base + kbp) * 32 + lane] = o0;
        ((float4*)g_Qf)[(base + kbp + 5) * 32 + lane] = o1;
        return;
    }
    int i2 = i - NQP;
    if (i2 >= NKP) return;
    int lane = i2 & 31, t = i2 >> 5;
    int kbp = t % 5, h = (t / 5) % NH, cbk = t / (5 * NH);
    int g = lane >> 2, tg = lane & 3;
    int rk = cbk * 8 + g;
    int cc = kbp * 8 + tg;
    const float* kr = g_K + (size_t)rk * DIM + h * HD;
    float x0[2] = {kr[cc], kr[cc + 4]};
    float x1[2] = {kr[cc + 40], kr[cc + 44]};
    int jc[2] = {cc, cc + 4};
    float2 o0, o1;
    float* o0p = &o0.x; float* o1p = &o1.x;
#pragma unroll
    for (int q = 0; q < 2; q++) {
        float c0 = cs[rk * HD + jc[q]],      s0 = sn[rk * HD + jc[q]];
        float c1 = cs[rk * HD + jc[q] + 40], s1 = sn[rk * HD + jc[q] + 40];
        o0p[q] = f2tf32(x0[q] * c0 - x1[q] * s0);
        o1p[q] = f2tf32(x1[q] * c1 + x0[q] * s1);
    }
    size_t base = ((size_t)(cbk * NH + h) * 10);
    ((float2*)g_Kf)[(base + kbp) * 32 + lane] = o0;
    ((float2*)g_Kf)[(base + kbp + 5) * 32 + lane] = o1;
}

// ---------------------------------------------------------------------------
// Persistent segmented flash attention, fragment-order operands (R16-proven).
// ---------------------------------------------------------------------------
#define ATT_GRID 296
#define AF_QF 0
#define AF_KF 5120
#define AF_VF 10240
#define AF_PF 15360
#define ATTN_SMEM (23552 * 4)   // 94208 B

__global__ __launch_bounds__(128)
void attn_mma(const int* __restrict__ cu)
{
    extern __shared__ float smf[];
    const uint32_t sb = (uint32_t)__cvta_generic_to_shared(smf);

    const int tid = threadIdx.x;
    const int warp = tid >> 5, lane = tid & 31;
    const int g = lane >> 2, tg = lane & 3;
    const int m0 = warp * 16;

    for (int item = blockIdx.x; item < (SEQ / 64) * NH; item += ATT_GRID) {
        const int qb = (item >> 4) * 64;
        const int h  = item & 15;
        const int rbq0 = qb >> 4;

        int ks = 0, ke = SEQ;
#pragma unroll
        for (int i = 0; i < 4; i++)
            if (qb >= cu[i] && qb < cu[i + 1]) { ks = cu[i]; ke = cu[i + 1]; }

        __syncthreads();

#pragma unroll
        for (int t = 0; t < 10; t++) {
            int idx = tid + t * 128;
            int blk = idx >> 5;
            int wq = blk / 10, kb = blk % 10;
            int l16 = idx & 31;
            cp16(sb + (uint32_t)(AF_QF + blk * 128 + l16 * 4) * 4u,
                 g_Qf + ((size_t)((rbq0 + wq) * NH + h) * 10 + kb) * 128 + l16 * 4);
        }
        asm volatile("cp.async.commit_group;\n");
        {
            int cbk0 = ks >> 3;
#pragma unroll
            for (int t = 0; t < 10; t++) {
                int idx = tid + t * 128;
                int blk = idx >> 4;
                int cbl = blk / 10, kb = blk % 10;
                int l8 = idx & 15;
                cp16(sb + (uint32_t)(AF_KF + blk * 64 + l8 * 4) * 4u,
                     g_Kf + ((size_t)((cbk0 + cbl) * NH + h) * 10 + kb) * 64 + l8 * 4);
            }
            asm volatile("cp.async.commit_group;\n");
        }

        float mrow[2] = {-1e30f, -1e30f};
        float lrow[2] = {0.f, 0.f};
        float o[10][4];
#pragma unroll
        for (int nt = 0; nt < 10; nt++)
#pragma unroll
            for (int r = 0; r < 4; r++) o[nt][r] = 0.f;

        for (int kt = ks; kt < ke; kt += 64) {
            int kn = min(64, ke - kt);
            asm volatile("cp.async.wait_group 0;\n");
            __syncthreads();

            {
                int kb20 = kt >> 3;
#pragma unroll
                for (int t = 0; t < 10; t++) {
                    int idx = tid + t * 128;
                    int blk = idx >> 4;
                    int db = blk >> 3, kb2l = blk & 7;
                    int l8 = idx & 15;
                    cp16(sb + (uint32_t)(AF_VF + blk * 64 + l8 * 4) * 4u,
                         g_Vtf + ((size_t)(h * 10 + db) * 256 + kb20 + kb2l) * 64 + l8 * 4);
                }
                asm volatile("cp.async.commit_group;\n");
            }

            float sacc[8][4];
#pragma unroll
            for (int nt = 0; nt < 8; nt++)
#pragma unroll
                for (int r = 0; r < 4; r++) sacc[nt][r] = 0.f;

#pragma unroll
            for (int ksp = 0; ksp < 10; ksp++) {
                uint32_t af[4], bf[8][2];
                float4 av = *(const float4*)(smf + AF_QF + (warp * 10 + ksp) * 128 + lane * 4);
                af[0] = __float_as_uint(av.x);
                af[1] = __float_as_uint(av.y);
                af[2] = __float_as_uint(av.z);
                af[3] = __float_as_uint(av.w);
#pragma unroll
                for (int nt = 0; nt < 8; nt++) {
                    float2 bv = *(const float2*)(smf + AF_KF + (nt * 10 + ksp) * 64 + lane * 2);
                    bf[nt][0] = __float_as_uint(bv.x);
                    bf[nt][1] = __float_as_uint(bv.y);
                }
#pragma unroll
                for (int nt = 0; nt < 8; nt++)
                    mma_tf32(sacc[nt], af, bf[nt]);
            }

            __syncthreads();

            if (kt + 64 < ke) {
                int cbk0 = (kt + 64) >> 3;
#pragma unroll
                for (int t = 0; t < 10; t++) {
                    int idx = tid + t * 128;
                    int blk = idx >> 4;
                    int cbl = blk / 10, kb = blk % 10;
                    int l8 = idx & 15;
                    cp16(sb + (uint32_t)(AF_KF + blk * 64 + l8 * 4) * 4u,
                         g_Kf + ((size_t)((cbk0 + cbl) * NH + h) * 10 + kb) * 64 + l8 * 4);
                }
            }
            asm volatile("cp.async.commit_group;\n");

            if (kn < 64) {
#pragma unroll
                for (int nt = 0; nt < 8; nt++) {
                    int c = nt * 8 + 2 * tg;
                    if (c >= kn)     { sacc[nt][0] = -1e30f; sacc[nt][2] = -1e30f; }
                    if (c + 1 >= kn) { sacc[nt][1] = -1e30f; sacc[nt][3] = -1e30f; }
                }
            }

#pragma unroll
            for (int half = 0; half < 2; half++) {
                const int b = half * 2;
                float mloc = -1e30f;
#pragma unroll
                for (int nt = 0; nt < 8; nt++)
                    mloc = fmaxf(mloc, fmaxf(sacc[nt][b], sacc[nt][b + 1]));
                mloc = fmaxf(mloc, __shfl_xor_sync(0xffffffffu, mloc, 1));
                mloc = fmaxf(mloc, __shfl_xor_sync(0xffffffffu, mloc, 2));
                float mn = fmaxf(mrow[half], mloc);
                float fac = __expf(mrow[half] - mn);
                mrow[half] = mn;
                float rs = 0.f;
#pragma unroll
                for (int nt = 0; nt < 8; nt++) {
                    float p0 = __expf(sacc[nt][b] - mn);
                    float p1 = __expf(sacc[nt][b + 1] - mn);
                    sacc[nt][b] = p0; sacc[nt][b + 1] = p1;
                    rs += p0 + p1;
                }
                rs += __shfl_xor_sync(0xffffffffu, rs, 1);
                rs += __shfl_xor_sync(0xffffffffu, rs, 2);
                lrow[half] = lrow[half] * fac + rs;
#pragma unroll
                for (int nt = 0; nt < 10; nt++) { o[nt][b] *= fac; o[nt][b + 1] *= fac; }
            }

            {
                float* pw = smf + AF_PF + warp * 2048;
                const int jj = 2 * tg;
                const int l0 = g * 4 + (jj & 3);
                const int l1 = g * 4 + ((jj + 1) & 3);
                const int cb = (tg < 2) ? 0 : 2;
#pragma unroll
                for (int nt = 0; nt < 8; nt++) {
                    pw[nt * 128 + l0 * 4 + cb]     = f2tf32(sacc[nt][0]);
                    pw[nt * 128 + l1 * 4 + cb]     = f2tf32(sacc[nt][1]);
                    pw[nt * 128 + l0 * 4 + cb + 1] = f2tf32(sacc[nt][2]);
                    pw[nt * 128 + l1 * 4 + cb + 1] = f2tf32(sacc[nt][3]);
                }
            }
            __syncwarp();

            asm volatile("cp.async.wait_group 1;\n");
            __syncthreads();

#pragma unroll
            for (int ksp = 0; ksp < 8; ksp++) {
                uint32_t af[4], bf[10][2];
                float4 av = *(const float4*)(smf + AF_PF + warp * 2048 + ksp * 128 + lane * 4);
                af[0] = __float_as_uint(av.x);
                af[1] = __float_as_uint(av.y);
                af[2] = __float_as_uint(av.z);
                af[3] = __float_as_uint(av.w);
#pragma unroll
                for (int nt = 0; nt < 10; nt++) {
                    float2 bv = *(const float2*)(smf + AF_VF + (nt * 8 + ksp) * 64 + lane * 2);
                    bf[nt][0] = __float_as_uint(bv.x);
                    bf[nt][1] = __float_as_uint(bv.y);
                }
#pragma unroll
                for (int nt = 0; nt < 10; nt++)
                    mma_tf32(o[nt], af, bf[nt]);
            }
        }

        const float inv0 = 1.f / lrow[0];
        const float inv1 = 1.f / lrow[1];
#pragma unroll
        for (int nt = 0; nt < 10; nt++) {
            int c = nt * 8 + 2 * tg;
            smf[(m0 + g) * 84 + c]         = o[nt][0] * inv0;
            smf[(m0 + g) * 84 + c + 1]     = o[nt][1] * inv0;
            smf[(m0 + 8 + g) * 84 + c]     = o[nt][2] * inv1;
            smf[(m0 + 8 + g) * 84 + c + 1] = o[nt][3] * inv1;
        }
        __syncwarp();

        const int rb = (qb + m0) >> 4;
#pragma unroll
        for (int nt = 0; nt < 10; nt++) {
            int kb = h * 10 + nt;
            float4 v;
            v.x = f2tf32(smf[(m0 + g) * 84 + nt * 8 + tg]);
            v.y = f2tf32(smf[(m0 + 8 + g) * 84 + nt * 8 + tg]);
            v.z = f2tf32(smf[(m0 + g) * 84 + nt * 8 + tg + 4]);
            v.w = f2tf32(smf[(m0 + 8 + g) * 84 + nt * 8 + tg + 4]);
            ((float4*)g_Aap)[(size_t)(rb * KBX + kb) * 32 + lane] = v;
        }
        __syncwarp();
    }
}

// ---------------------------------------------------------------------------
extern "C" void kernel_launch(void* const* d_in, const int* in_sizes, int n_in,
                              void* d_out, int out_size)
{
    const float* X  = (const float*)d_in[0];
    const float* Wq = (const float*)d_in[1];
    const float* bq = (const float*)d_in[2];
    const float* Wk = (const float*)d_in[3];
    const float* bk = (const float*)d_in[4];
    const float* Wv = (const float*)d_in[5];
    const float* bv = (const float*)d_in[6];
    const float* Wo = (const float*)d_in[7];
    const float* bo = (const float*)d_in[8];
    const float* cs = (const float*)d_in[9];
    const float* sn = (const float*)d_in[10];
    const int*   cu = (const int*)d_in[11];
    float* out = (float*)d_out;

    void *pXap, *pAap;
    cudaGetSymbolAddress(&pXap, g_Xap);
    cudaGetSymbolAddress(&pAap, g_Aap);

    cudaFuncSetAttribute(gemm_qkv,
                         cudaFuncAttributeMaxDynamicSharedMemorySize, GEMM_SMEM);
    cudaFuncSetAttribute(gemm_o,
                         cudaFuncAttributeMaxDynamicSharedMemorySize, GEMM_SMEM);
    cudaFuncSetAttribute(attn_mma,
                         cudaFuncAttributeMaxDynamicSharedMemorySize, ATTN_SMEM);

    const int ntot = NXP + 4 * NWP;

    permute_all<<<(ntot + 255) / 256, 256>>>(X, Wq, Wk, Wv, Wo);

    dim3 gq(48, SEQ / BM);             // 768 CTAs, occ 2
    gemm_qkv<<<gq, 256, GEMM_SMEM>>>((const float*)pXap, bq, bk, bv);

    const int rtot = NQP + NKP;
    rope_frag<<<(rtot + 255) / 256, 256>>>(cs, sn);

    attn_mma<<<ATT_GRID, 128, ATTN_SMEM>>>(cu);

    dim3 go(16, SEQ / BM);             // 256 CTAs, occ 2
    gemm_o<<<go, 256, GEMM_SMEM>>>((const float*)pAap, bo, out);
}